// round 10
// baseline (speedup 1.0000x reference)
#include <cuda_runtime.h>
#include <cuda_fp16.h>
#include <cstdint>

// ---------------------------------------------------------------------------
// QuantizedLinear: y[t,o] = scale[o] * sum_k x[t,k]*qW[o,k] + bias[o]
// TOKENS=256, IN_F=4096, OUT_F=14336. qW int32 in [0,127) -> exact in fp16.
// R9 (resubmit): M128xN64 tiles -> 448 CTAs (3/SM, balanced on 148 SMs).
// W path: LDG.128 -> reg convert -> STS (no int SMEM staging). fp16 m16n8k16.
// ---------------------------------------------------------------------------

#define TOKENS 256
#define IN_F   4096
#define OUT_F  14336

#define M_TILE 128
#define N_TILE 64
#define KC     32                 // K elems per stage
#define NST    (IN_F / KC)        // 128 stages
#define S      3                  // A-tile cp.async depth
#define NTHREADS 256

// fp16 tile rows: 32 halfs = 64B data + 16B pad = 80B. Bank stride 20 ->
// every ldmatrix 8-row x 16B phase covers all 32 banks once (conflict-free).
#define ROWB      80
#define A_STAGE_B (M_TILE * ROWB)     // 10240
#define BF_BUF_B  (N_TILE * ROWB)     // 5120

#define SM_SCALE 0
#define SM_BIAS  256
#define SM_A0    512
#define SM_BF0   (SM_A0 + S * A_STAGE_B)     // 31232
#define SM_TOTAL (SM_BF0 + 2 * BF_BUF_B)     // 41472 (x3 CTAs = 124416 OK)

__device__ __half g_x_f16[TOKENS * IN_F];

// ---------------------------------------------------------------------------
__device__ __forceinline__ uint32_t smem_u32(const void* p) {
    uint32_t a;
    asm("{ .reg .u64 t; cvta.to.shared.u64 t, %1; cvt.u32.u64 %0, t; }"
        : "=r"(a) : "l"(p));
    return a;
}

#define CP_ASYNC16(dst, src) \
    asm volatile("cp.async.cg.shared.global [%0], [%1], 16;" :: "r"(dst), "l"(src))
#define CP_COMMIT() asm volatile("cp.async.commit_group;" ::: "memory")
#define CP_WAIT(n)  asm volatile("cp.async.wait_group %0;" :: "n"(n) : "memory")

#define LDMX4(r0, r1, r2, r3, addr) \
    asm volatile("ldmatrix.sync.aligned.m8n8.x4.shared.b16 {%0,%1,%2,%3}, [%4];" \
                 : "=r"(r0), "=r"(r1), "=r"(r2), "=r"(r3) : "r"(addr))

__device__ __forceinline__ void mma_f16(float* c, const uint32_t* a, const uint32_t* b) {
    asm volatile(
        "mma.sync.aligned.m16n8k16.row.col.f32.f16.f16.f32 "
        "{%0,%1,%2,%3}, {%4,%5,%6,%7}, {%8,%9}, {%0,%1,%2,%3};"
        : "+f"(c[0]), "+f"(c[1]), "+f"(c[2]), "+f"(c[3])
        : "r"(a[0]), "r"(a[1]), "r"(a[2]), "r"(a[3]), "r"(b[0]), "r"(b[1]));
}

// Exact int(0..126) pair -> fp16x2: gather low bytes, OR 0x6400 (=1024.0,
// ULP=1 on [1024,2048)), subtract 1024. 3 ops per 2 elements.
__device__ __forceinline__ uint32_t int2_to_h2(uint32_t lo, uint32_t hi) {
    uint32_t p;
    asm("prmt.b32 %0, %1, %2, 0x5410;" : "=r"(p) : "r"(lo), "r"(hi));
    p = (p & 0x00FF00FFu) | 0x64006400u;
    uint32_t r;
    asm("sub.rn.f16x2 %0, %1, %2;" : "=r"(r) : "r"(p), "r"(0x64006400u));
    return r;
}

// ---------------------------------------------------------------------------
__global__ void __launch_bounds__(256) prep_x_kernel(const float* __restrict__ x) {
    int i = blockIdx.x * blockDim.x + threadIdx.x;
    if (i < TOKENS * IN_F) g_x_f16[i] = __float2half_rn(x[i]);
}

// ---------------------------------------------------------------------------
__global__ void __launch_bounds__(NTHREADS, 3) qlin_gemm_kernel(
    const int*   __restrict__ W,
    const float* __restrict__ scale,
    const float* __restrict__ bias,
    float*       __restrict__ out)
{
    extern __shared__ char smem[];
    const uint32_t sb = smem_u32(smem);
    const int tid = threadIdx.x;
    const int wid = tid >> 5;
    const int lid = tid & 31;
    const int g   = lid >> 2;
    const int t   = lid & 3;
    const int wm  = wid >> 1;    // 4 M warp-rows (32 tokens each)
    const int wn  = wid & 1;     // 2 N warp-cols (32 feats each)
    const int n0  = blockIdx.x * N_TILE;
    const int m0  = blockIdx.y * M_TILE;

    if (tid < N_TILE) {
        ((float*)(smem + SM_SCALE))[tid] = scale[n0 + tid];
        ((float*)(smem + SM_BIAS))[tid]  = bias[n0 + tid];
    }

    // ---- A cp.async chunk mapping (128 rows x 64B = 512 chunks, 2/thread) --
    uint32_t aSoff[2]; const __half* aG[2];
#pragma unroll
    for (int i = 0; i < 2; i++) {
        int c = tid + i * NTHREADS;
        int row = c >> 2, ca = c & 3;
        aSoff[i] = (uint32_t)(row * ROWB + ca * 16);
        aG[i]    = g_x_f16 + (size_t)(m0 + row) * IN_F + ca * 8;
    }
    // ---- B LDG mapping (64 rows x 128B = 512 chunks, 2/thread) ------------
    uint32_t bFoff[2]; const int4* bG[2];
#pragma unroll
    for (int i = 0; i < 2; i++) {
        int c = tid + i * NTHREADS;
        int row = c >> 3, cb = c & 7;
        bFoff[i] = (uint32_t)(row * ROWB + cb * 8);
        bG[i]    = reinterpret_cast<const int4*>(
                       W + (size_t)(n0 + row) * IN_F + cb * 4);
    }

    // ---- prologue ---------------------------------------------------------
#pragma unroll
    for (int s = 0; s < 2; s++) {
        const uint32_t ab = sb + SM_A0 + s * A_STAGE_B;
        const int kb = s * KC;
#pragma unroll
        for (int i = 0; i < 2; i++) CP_ASYNC16(ab + aSoff[i], aG[i] + kb);
        CP_COMMIT();
    }
    int4 wreg[2];                       // W stage-0
#pragma unroll
    for (int i = 0; i < 2; i++) wreg[i] = bG[i][0];

    float acc[2][4][4];
#pragma unroll
    for (int i = 0; i < 2; i++)
#pragma unroll
        for (int j = 0; j < 4; j++)
#pragma unroll
            for (int c = 0; c < 4; c++) acc[i][j][c] = 0.0f;

    // ---- ldmatrix bases ---------------------------------------------------
    // A x4 (16 rows x 16 k): lane groups -> (r+0,k0)/(r+8,k0)/(r+0,k8)/(r+8,k8)
    const uint32_t aLM = sb + SM_A0 +
        (uint32_t)((wm * 32 + (lid & 7) + 8 * ((lid >> 3) & 1)) * ROWB
                   + (lid >> 4) * 16);
    // B x4 (16 n-rows x 16 k): groups -> (n+0,k0)/(n+0,k8)/(n+8,k0)/(n+8,k8)
    const uint32_t bLM = sb + SM_BF0 +
        (uint32_t)((wn * 32 + (lid & 7) + 8 * (lid >> 4)) * ROWB
                   + ((lid >> 3) & 1) * 16);

    // ---- main loop --------------------------------------------------------
#pragma unroll 1
    for (int s = 0; s < NST; s++) {
        if (s < NST - 1) { CP_WAIT(1); } else { CP_WAIT(0); }   // A(s) ready

        // convert W(s) regs -> fp16 buffer (parity s&1). Previous reader of
        // this parity was compute(s-2), retired before barrier(s-1).
        {
            char* bf = smem + SM_BF0 + (s & 1) * BF_BUF_B;
#pragma unroll
            for (int i = 0; i < 2; i++) {
                uint2 p;
                p.x = int2_to_h2((uint32_t)wreg[i].x, (uint32_t)wreg[i].y);
                p.y = int2_to_h2((uint32_t)wreg[i].z, (uint32_t)wreg[i].w);
                *reinterpret_cast<uint2*>(bf + bFoff[i]) = p;
            }
        }
        __syncthreads();

        // W(s+1) -> regs (latency covered by compute(s) + next barrier)
        if (s + 1 < NST) {
            const int kb4 = (s + 1) * (KC / 4);
#pragma unroll
            for (int i = 0; i < 2; i++) wreg[i] = bG[i][kb4];
        }
        // A(s+2) -> slot (s+2)%3 (freed by compute(s-1), ordered by barrier)
        if (s + 2 < NST) {
            const uint32_t ab = sb + SM_A0 + ((s + 2) % S) * A_STAGE_B;
            const int kb = (s + 2) * KC;
#pragma unroll
            for (int i = 0; i < 2; i++) CP_ASYNC16(ab + aSoff[i], aG[i] + kb);
            CP_COMMIT();
        }

        // compute stage s: two k16 steps
        const uint32_t aS = aLM + (s % S) * A_STAGE_B;
        const uint32_t bS = bLM + (s & 1) * BF_BUF_B;
#pragma unroll
        for (int kk = 0; kk < 2; kk++) {
            const uint32_t ko = (uint32_t)(kk * 32);
            uint32_t a[2][4], b[4][2];
#pragma unroll
            for (int i = 0; i < 2; i++)
                LDMX4(a[i][0], a[i][1], a[i][2], a[i][3],
                      aS + (uint32_t)(i * 16 * ROWB) + ko);
#pragma unroll
            for (int jp = 0; jp < 2; jp++)
                LDMX4(b[2 * jp][0], b[2 * jp][1], b[2 * jp + 1][0], b[2 * jp + 1][1],
                      bS + (uint32_t)(jp * 16 * ROWB) + ko);
#pragma unroll
            for (int i = 0; i < 2; i++)
#pragma unroll
                for (int j = 0; j < 4; j++)
                    mma_f16(acc[i][j], a[i], b[j]);
        }
    }

    // ---- epilogue ---------------------------------------------------------
    const float* s_sc = (const float*)(smem + SM_SCALE);
    const float* s_bi = (const float*)(smem + SM_BIAS);
#pragma unroll
    for (int i = 0; i < 2; i++) {
        const int m = m0 + wm * 32 + i * 16 + g;
#pragma unroll
        for (int j = 0; j < 4; j++) {
            const int nl = wn * 32 + j * 8 + 2 * t;
            const float sc0 = s_sc[nl],     bi0 = s_bi[nl];
            const float sc1 = s_sc[nl + 1], bi1 = s_bi[nl + 1];
            float2 v0 = { acc[i][j][0] * sc0 + bi0, acc[i][j][1] * sc1 + bi1 };
            float2 v1 = { acc[i][j][2] * sc0 + bi0, acc[i][j][3] * sc1 + bi1 };
            *reinterpret_cast<float2*>(out + (size_t)m * OUT_F + n0 + nl) = v0;
            *reinterpret_cast<float2*>(out + (size_t)(m + 8) * OUT_F + n0 + nl) = v1;
        }
    }
}

// ---------------------------------------------------------------------------
extern "C" void kernel_launch(void* const* d_in, const int* in_sizes, int n_in,
                              void* d_out, int out_size) {
    const float* x     = (const float*)d_in[0];
    const int*   W     = (const int*)  d_in[1];
    const float* scale = (const float*)d_in[2];
    const float* bias  = (const float*)d_in[3];
    float*       out   = (float*)d_out;

    (void)in_sizes; (void)n_in; (void)out_size;

    cudaFuncSetAttribute(qlin_gemm_kernel,
                         cudaFuncAttributeMaxDynamicSharedMemorySize, SM_TOTAL);

    prep_x_kernel<<<(TOKENS * IN_F + 255) / 256, 256>>>(x);

    dim3 grid(OUT_F / N_TILE, TOKENS / M_TILE);   // (224, 2) = 448 CTAs, 3/SM
    qlin_gemm_kernel<<<grid, NTHREADS, SM_TOTAL>>>(W, scale, bias, out);
}

// round 12
// speedup vs baseline: 1.2633x; 1.2633x over previous
#include <cuda_runtime.h>
#include <cuda_fp16.h>
#include <cstdint>

// ---------------------------------------------------------------------------
// QuantizedLinear: y[t,o] = scale[o] * sum_k x[t,k]*qW[o,k] + bias[o]
// TOKENS=256, IN_F=4096, OUT_F=14336. qW int32 in [0,127) -> exact in fp16.
// R11 (resubmit): R8 kernel (128x128 tile, fp16 m16n8k16, ldmatrix, magic
// convert, 2 CTAs/SM) + SPLIT-K=2 for SM load balance: 448 CTAs x 64 stages.
// k-half 0 writes scale*acc+bias to out; k-half 1 writes scale*acc to a
// partial buffer; a float4 combine kernel adds them. Deterministic.
// ---------------------------------------------------------------------------

#define TOKENS 256
#define IN_F   4096
#define OUT_F  14336

#define M_TILE 128
#define N_TILE 128
#define KC     32                 // K elems per stage
#define KHALF  (IN_F / 2)         // 2048
#define NSTH   (KHALF / KC)       // 64 stages per k-half
#define S      3                  // cp.async pipeline depth
#define NTHREADS 256

// fp16 tile rows: 32 halfs = 64B data + 16B pad = 80B. Bank stride 20 ->
// every ldmatrix 8-row x 16B phase covers all 32 banks once (conflict-free).
#define ROWB      80
#define A_STAGE_B (M_TILE * ROWB)     // 10240
#define BI_STAGE_B (N_TILE * 128)     // 16384 (int32 staging: 32*4B rows)
#define BF_BUF_B  (N_TILE * ROWB)     // 10240

#define SM_SCALE 0
#define SM_BIAS  512
#define SM_A0    1024
#define SM_BI0   (SM_A0 + S * A_STAGE_B)     // 31744
#define SM_BF0   (SM_BI0 + S * BI_STAGE_B)   // 80896
#define SM_TOTAL (SM_BF0 + 2 * BF_BUF_B)     // 101376 (x2 CTAs fits 227KB)

__device__ __half g_x_f16[TOKENS * IN_F];
__device__ float  g_part[TOKENS * OUT_F];    // k-half-1 partials (14.7MB)

// ---------------------------------------------------------------------------
__device__ __forceinline__ uint32_t smem_u32(const void* p) {
    uint32_t a;
    asm("{ .reg .u64 t; cvta.to.shared.u64 t, %1; cvt.u32.u64 %0, t; }"
        : "=r"(a) : "l"(p));
    return a;
}

#define CP_ASYNC16(dst, src) \
    asm volatile("cp.async.cg.shared.global [%0], [%1], 16;" :: "r"(dst), "l"(src))
#define CP_COMMIT() asm volatile("cp.async.commit_group;" ::: "memory")
#define CP_WAIT(n)  asm volatile("cp.async.wait_group %0;" :: "n"(n) : "memory")

#define LDMX4(r0, r1, r2, r3, addr) \
    asm volatile("ldmatrix.sync.aligned.m8n8.x4.shared.b16 {%0,%1,%2,%3}, [%4];" \
                 : "=r"(r0), "=r"(r1), "=r"(r2), "=r"(r3) : "r"(addr))

__device__ __forceinline__ void mma_f16(float* c, const uint32_t* a, const uint32_t* b) {
    asm volatile(
        "mma.sync.aligned.m16n8k16.row.col.f32.f16.f16.f32 "
        "{%0,%1,%2,%3}, {%4,%5,%6,%7}, {%8,%9}, {%0,%1,%2,%3};"
        : "+f"(c[0]), "+f"(c[1]), "+f"(c[2]), "+f"(c[3])
        : "r"(a[0]), "r"(a[1]), "r"(a[2]), "r"(a[3]), "r"(b[0]), "r"(b[1]));
}

// Exact int(0..126) pair -> fp16x2: gather low bytes, OR 0x6400 (=1024.0 bits,
// ULP=1 in [1024,2048)), subtract 1024. 3 ops per 2 elements.
__device__ __forceinline__ uint32_t int2_to_h2(uint32_t lo, uint32_t hi) {
    uint32_t p;
    asm("prmt.b32 %0, %1, %2, 0x5410;" : "=r"(p) : "r"(lo), "r"(hi));
    p = (p & 0x00FF00FFu) | 0x64006400u;
    uint32_t r;
    asm("sub.rn.f16x2 %0, %1, %2;" : "=r"(r) : "r"(p), "r"(0x64006400u));
    return r;
}

// ---------------------------------------------------------------------------
__global__ void __launch_bounds__(256) prep_x_kernel(const float* __restrict__ x) {
    int i = blockIdx.x * blockDim.x + threadIdx.x;
    if (i < TOKENS * IN_F) g_x_f16[i] = __float2half_rn(x[i]);
}

// out += partial (vectorized)
__global__ void __launch_bounds__(256) combine_kernel(float* __restrict__ out) {
    int i = blockIdx.x * blockDim.x + threadIdx.x;   // float4 index
    const float4* p4 = reinterpret_cast<const float4*>(g_part);
    float4*       o4 = reinterpret_cast<float4*>(out);
    float4 a = o4[i], b = p4[i];
    a.x += b.x; a.y += b.y; a.z += b.z; a.w += b.w;
    o4[i] = a;
}

// ---------------------------------------------------------------------------
__global__ void __launch_bounds__(NTHREADS, 2) qlin_gemm_kernel(
    const int*   __restrict__ W,
    const float* __restrict__ scale,
    const float* __restrict__ bias,
    float*       __restrict__ out)
{
    extern __shared__ char smem[];
    const uint32_t sb = smem_u32(smem);
    const int tid = threadIdx.x;
    const int wid = tid >> 5;
    const int lid = tid & 31;
    const int g   = lid >> 2;
    const int t   = lid & 3;
    const int wm  = wid & 1;     // 2 M warp-rows (64 tokens)
    const int wn  = wid >> 1;    // 4 N warp-cols (32 feats)
    const int n0  = blockIdx.x * N_TILE;
    const int m0  = blockIdx.y * M_TILE;
    const int kh  = blockIdx.z;              // k-half: 0 or 1
    const int k0  = kh * KHALF;              // element offset into K

    if (tid < N_TILE) {
        ((float*)(smem + SM_SCALE))[tid] = scale[n0 + tid];
        ((float*)(smem + SM_BIAS))[tid]  = bias[n0 + tid];
    }

    // ---- cp.async chunk mapping ------------------------------------------
    uint32_t aSoff[2]; const __half* aG[2];
#pragma unroll
    for (int i = 0; i < 2; i++) {
        int c = tid + i * NTHREADS;         // 0..511
        int row = c >> 2, ca = c & 3;
        aSoff[i] = (uint32_t)(row * ROWB + ca * 16);
        aG[i]    = g_x_f16 + (size_t)(m0 + row) * IN_F + k0 + ca * 8;
    }
    uint32_t bIoff[4], bFoff[4]; const int* bG[4];
#pragma unroll
    for (int i = 0; i < 4; i++) {
        int c = tid + i * NTHREADS;         // 0..1023
        int row = c >> 3, cb = c & 7;
        bIoff[i] = (uint32_t)(row * 128 + cb * 16);
        bFoff[i] = (uint32_t)(row * ROWB + cb * 8);
        bG[i]    = W + (size_t)(n0 + row) * IN_F + k0 + cb * 4;
    }

    // ---- prologue ---------------------------------------------------------
#pragma unroll
    for (int s = 0; s < S - 1; s++) {
        const uint32_t ab = sb + SM_A0  + s * A_STAGE_B;
        const uint32_t bb = sb + SM_BI0 + s * BI_STAGE_B;
        const int kb = s * KC;
#pragma unroll
        for (int i = 0; i < 2; i++) CP_ASYNC16(ab + aSoff[i], aG[i] + kb);
#pragma unroll
        for (int i = 0; i < 4; i++) CP_ASYNC16(bb + bIoff[i], bG[i] + kb);
        CP_COMMIT();
    }

    float acc[4][4][4];
#pragma unroll
    for (int i = 0; i < 4; i++)
#pragma unroll
        for (int j = 0; j < 4; j++)
#pragma unroll
            for (int c = 0; c < 4; c++) acc[i][j][c] = 0.0f;

    // ---- per-thread ldmatrix bases ---------------------------------------
    // A x4 (16 rows x 16 k): lane groups -> (r+0,k0)/(r+8,k0)/(r+0,k8)/(r+8,k8)
    const uint32_t aLM = sb + SM_A0 +
        (uint32_t)((wm * 64 + (lid & 7) + 8 * ((lid >> 3) & 1)) * ROWB
                   + (lid >> 4) * 16);
    // B x4 (16 n-rows x 16 k): groups -> (n+0,k0)/(n+0,k8)/(n+8,k0)/(n+8,k8)
    const uint32_t bLM = sb + SM_BF0 +
        (uint32_t)((wn * 32 + (lid & 7) + 8 * (lid >> 4)) * ROWB
                   + ((lid >> 3) & 1) * 16);

    // ---- main loop (64 stages per k-half) ---------------------------------
#pragma unroll 1
    for (int s = 0; s < NSTH; s++) {
        const int slot = s % S;

        if (s + S - 1 < NSTH) { CP_WAIT(S - 2); } else { CP_WAIT(0); }

        // convert stage-s W ints -> fp16 buffer (parity s&1). Previous reader
        // of this parity was compute(s-2), retired before barrier(s-1).
        {
            char* bi = smem + SM_BI0 + slot * BI_STAGE_B;
            char* bf = smem + SM_BF0 + (s & 1) * BF_BUF_B;
#pragma unroll
            for (int i = 0; i < 4; i++) {
                int4 v = *reinterpret_cast<const int4*>(bi + bIoff[i]);
                uint2 p;
                p.x = int2_to_h2((uint32_t)v.x, (uint32_t)v.y);
                p.y = int2_to_h2((uint32_t)v.z, (uint32_t)v.w);
                *reinterpret_cast<uint2*>(bf + bFoff[i]) = p;
            }
        }
        __syncthreads();

        // prefetch stage s+S-1 (slot freed by compute(s-1), ordered above)
        if (s + S - 1 < NSTH) {
            const int ps = s + S - 1;
            const int pb = ps % S;
            const uint32_t ab = sb + SM_A0  + pb * A_STAGE_B;
            const uint32_t bb = sb + SM_BI0 + pb * BI_STAGE_B;
            const int kb = ps * KC;
#pragma unroll
            for (int i = 0; i < 2; i++) CP_ASYNC16(ab + aSoff[i], aG[i] + kb);
#pragma unroll
            for (int i = 0; i < 4; i++) CP_ASYNC16(bb + bIoff[i], bG[i] + kb);
            CP_COMMIT();
        }

        // compute stage s: two k16 steps, fragments via ldmatrix.x4
        const uint32_t aS = aLM + slot * A_STAGE_B;
        const uint32_t bS = bLM + (s & 1) * BF_BUF_B;
#pragma unroll
        for (int kk = 0; kk < 2; kk++) {
            const uint32_t ko = (uint32_t)(kk * 32);
            uint32_t a[4][4], b[4][2];
#pragma unroll
            for (int i = 0; i < 4; i++)
                LDMX4(a[i][0], a[i][1], a[i][2], a[i][3],
                      aS + (uint32_t)(i * 16 * ROWB) + ko);
#pragma unroll
            for (int jp = 0; jp < 2; jp++)
                LDMX4(b[2 * jp][0], b[2 * jp][1], b[2 * jp + 1][0], b[2 * jp + 1][1],
                      bS + (uint32_t)(jp * 16 * ROWB) + ko);
#pragma unroll
            for (int i = 0; i < 4; i++)
#pragma unroll
                for (int j = 0; j < 4; j++)
                    mma_f16(acc[i][j], a[i], b[j]);
        }
    }

    // ---- epilogue ---------------------------------------------------------
    // kh==0: out = scale*acc + bias.  kh==1: part = scale*acc.
    const float* s_sc = (const float*)(smem + SM_SCALE);
    const float* s_bi = (const float*)(smem + SM_BIAS);
    float* dst = (kh == 0) ? out : g_part;
#pragma unroll
    for (int i = 0; i < 4; i++) {
        const int m = m0 + wm * 64 + i * 16 + g;
#pragma unroll
        for (int j = 0; j < 4; j++) {
            const int nl = wn * 32 + j * 8 + 2 * t;
            const float sc0 = s_sc[nl],     sc1 = s_sc[nl + 1];
            const float bi0 = (kh == 0) ? s_bi[nl]     : 0.0f;
            const float bi1 = (kh == 0) ? s_bi[nl + 1] : 0.0f;
            float2 v0 = { acc[i][j][0] * sc0 + bi0, acc[i][j][1] * sc1 + bi1 };
            float2 v1 = { acc[i][j][2] * sc0 + bi0, acc[i][j][3] * sc1 + bi1 };
            *reinterpret_cast<float2*>(dst + (size_t)m * OUT_F + n0 + nl) = v0;
            *reinterpret_cast<float2*>(dst + (size_t)(m + 8) * OUT_F + n0 + nl) = v1;
        }
    }
}

// ---------------------------------------------------------------------------
extern "C" void kernel_launch(void* const* d_in, const int* in_sizes, int n_in,
                              void* d_out, int out_size) {
    const float* x     = (const float*)d_in[0];
    const int*   W     = (const int*)  d_in[1];
    const float* scale = (const float*)d_in[2];
    const float* bias  = (const float*)d_in[3];
    float*       out   = (float*)d_out;

    (void)in_sizes; (void)n_in; (void)out_size;

    cudaFuncSetAttribute(qlin_gemm_kernel,
                         cudaFuncAttributeMaxDynamicSharedMemorySize, SM_TOTAL);

    prep_x_kernel<<<(TOKENS * IN_F + 255) / 256, 256>>>(x);

    dim3 grid(OUT_F / N_TILE, TOKENS / M_TILE, 2);   // (112, 2, 2) = 448 CTAs
    qlin_gemm_kernel<<<grid, NTHREADS, SM_TOTAL>>>(W, scale, bias, out);

    // out += k-half-1 partials (float4: 3.67M floats -> 917504 float4s)
    combine_kernel<<<(TOKENS * OUT_F / 4) / 256, 256>>>(out);
}

// round 13
// speedup vs baseline: 1.3496x; 1.0684x over previous
#include <cuda_runtime.h>
#include <cuda_fp16.h>
#include <cstdint>

// ---------------------------------------------------------------------------
// QuantizedLinear: y[t,o] = scale[o] * sum_k x[t,k]*qW[o,k] + bias[o]
// TOKENS=256, IN_F=4096, OUT_F=14336. qW int32 in [0,127) -> exact in fp16.
// R13: R8 config (128x128 tile, fp16 m16n8k16, ldmatrix, magic convert,
// 2 CTAs/SM) with the int->fp16 convert SOFTWARE-PIPELINED one stage ahead:
// loop body = prefetch(s+3), wait, convert(s+1), compute(s), barrier.
// Convert is off the wait->compute critical path and interleaves with mma.
// ---------------------------------------------------------------------------

#define TOKENS 256
#define IN_F   4096
#define OUT_F  14336

#define M_TILE 128
#define N_TILE 128
#define KC     32                 // K elems per stage
#define NST    (IN_F / KC)        // 128 stages
#define S_A    4                  // A-tile slots
#define S_BI   3                  // B int32 staging slots
#define NTHREADS 256

// fp16 tile rows: 32 halfs = 64B data + 16B pad = 80B. Bank stride 20 ->
// every ldmatrix 8-row x 16B phase covers all 32 banks once (conflict-free).
#define ROWB      80
#define A_STAGE_B (M_TILE * ROWB)     // 10240
#define BI_STAGE_B (N_TILE * 128)     // 16384 (int32 staging: 32*4B rows)
#define BF_BUF_B  (N_TILE * ROWB)     // 10240

#define SM_SCALE 0
#define SM_BIAS  512
#define SM_A0    1024
#define SM_BI0   (SM_A0 + S_A * A_STAGE_B)     // 41984
#define SM_BF0   (SM_BI0 + S_BI * BI_STAGE_B)  // 91136
#define SM_TOTAL (SM_BF0 + 2 * BF_BUF_B)       // 111616 (x2 CTAs = 223232)

__device__ __half g_x_f16[TOKENS * IN_F];

// ---------------------------------------------------------------------------
__device__ __forceinline__ uint32_t smem_u32(const void* p) {
    uint32_t a;
    asm("{ .reg .u64 t; cvta.to.shared.u64 t, %1; cvt.u32.u64 %0, t; }"
        : "=r"(a) : "l"(p));
    return a;
}

#define CP_ASYNC16(dst, src) \
    asm volatile("cp.async.cg.shared.global [%0], [%1], 16;" :: "r"(dst), "l"(src))
#define CP_COMMIT() asm volatile("cp.async.commit_group;" ::: "memory")
#define CP_WAIT(n)  asm volatile("cp.async.wait_group %0;" :: "n"(n) : "memory")

#define LDMX4(r0, r1, r2, r3, addr) \
    asm volatile("ldmatrix.sync.aligned.m8n8.x4.shared.b16 {%0,%1,%2,%3}, [%4];" \
                 : "=r"(r0), "=r"(r1), "=r"(r2), "=r"(r3) : "r"(addr))

__device__ __forceinline__ void mma_f16(float* c, const uint32_t* a, const uint32_t* b) {
    asm volatile(
        "mma.sync.aligned.m16n8k16.row.col.f32.f16.f16.f32 "
        "{%0,%1,%2,%3}, {%4,%5,%6,%7}, {%8,%9}, {%0,%1,%2,%3};"
        : "+f"(c[0]), "+f"(c[1]), "+f"(c[2]), "+f"(c[3])
        : "r"(a[0]), "r"(a[1]), "r"(a[2]), "r"(a[3]), "r"(b[0]), "r"(b[1]));
}

// Exact int(0..126) pair -> fp16x2: gather low bytes, OR 0x6400 (=1024.0 bits,
// ULP=1 in [1024,2048)), subtract 1024. 3 ops per 2 elements.
__device__ __forceinline__ uint32_t int2_to_h2(uint32_t lo, uint32_t hi) {
    uint32_t p;
    asm("prmt.b32 %0, %1, %2, 0x5410;" : "=r"(p) : "r"(lo), "r"(hi));
    p = (p & 0x00FF00FFu) | 0x64006400u;
    uint32_t r;
    asm("sub.rn.f16x2 %0, %1, %2;" : "=r"(r) : "r"(p), "r"(0x64006400u));
    return r;
}

// ---------------------------------------------------------------------------
__global__ void __launch_bounds__(256) prep_x_kernel(const float* __restrict__ x) {
    int i = blockIdx.x * blockDim.x + threadIdx.x;
    if (i < TOKENS * IN_F) g_x_f16[i] = __float2half_rn(x[i]);
}

// ---------------------------------------------------------------------------
__global__ void __launch_bounds__(NTHREADS, 2) qlin_gemm_kernel(
    const int*   __restrict__ W,
    const float* __restrict__ scale,
    const float* __restrict__ bias,
    float*       __restrict__ out)
{
    extern __shared__ char smem[];
    const uint32_t sb = smem_u32(smem);
    const int tid = threadIdx.x;
    const int wid = tid >> 5;
    const int lid = tid & 31;
    const int g   = lid >> 2;
    const int t   = lid & 3;
    const int wm  = wid & 1;     // 2 M warp-rows (64 tokens)
    const int wn  = wid >> 1;    // 4 N warp-cols (32 feats)
    const int n0  = blockIdx.x * N_TILE;
    const int m0  = blockIdx.y * M_TILE;

    if (tid < N_TILE) {
        ((float*)(smem + SM_SCALE))[tid] = scale[n0 + tid];
        ((float*)(smem + SM_BIAS))[tid]  = bias[n0 + tid];
    }

    // ---- cp.async chunk mapping ------------------------------------------
    uint32_t aSoff[2]; const __half* aG[2];
#pragma unroll
    for (int i = 0; i < 2; i++) {
        int c = tid + i * NTHREADS;         // 0..511
        int row = c >> 2, ca = c & 3;
        aSoff[i] = (uint32_t)(row * ROWB + ca * 16);
        aG[i]    = g_x_f16 + (size_t)(m0 + row) * IN_F + ca * 8;
    }
    uint32_t bIoff[4], bFoff[4]; const int* bG[4];
#pragma unroll
    for (int i = 0; i < 4; i++) {
        int c = tid + i * NTHREADS;         // 0..1023
        int row = c >> 3, cb = c & 7;
        bIoff[i] = (uint32_t)(row * 128 + cb * 16);
        bFoff[i] = (uint32_t)(row * ROWB + cb * 8);
        bG[i]    = W + (size_t)(n0 + row) * IN_F + cb * 4;
    }

    // ---- prologue: stages 0..2 in flight; convert(0) ----------------------
#pragma unroll
    for (int s = 0; s < 3; s++) {
        const uint32_t ab = sb + SM_A0  + s * A_STAGE_B;          // slot s
        const uint32_t bb = sb + SM_BI0 + s * BI_STAGE_B;         // slot s
        const int kb = s * KC;
#pragma unroll
        for (int i = 0; i < 2; i++) CP_ASYNC16(ab + aSoff[i], aG[i] + kb);
#pragma unroll
        for (int i = 0; i < 4; i++) CP_ASYNC16(bb + bIoff[i], bG[i] + kb);
        CP_COMMIT();
    }
    CP_WAIT(1);                     // stages 0,1 arrived (own groups)
    {
        char* bi = smem + SM_BI0;                     // BI slot 0
        char* bf = smem + SM_BF0;                     // Bf parity 0
#pragma unroll
        for (int i = 0; i < 4; i++) {
            int4 v = *reinterpret_cast<const int4*>(bi + bIoff[i]);
            uint2 p;
            p.x = int2_to_h2((uint32_t)v.x, (uint32_t)v.y);
            p.y = int2_to_h2((uint32_t)v.z, (uint32_t)v.w);
            *reinterpret_cast<uint2*>(bf + bFoff[i]) = p;
        }
    }
    __syncthreads();

    float acc[4][4][4];
#pragma unroll
    for (int i = 0; i < 4; i++)
#pragma unroll
        for (int j = 0; j < 4; j++)
#pragma unroll
            for (int c = 0; c < 4; c++) acc[i][j][c] = 0.0f;

    // ---- per-thread ldmatrix bases ---------------------------------------
    // A x4 (16 rows x 16 k): lane groups -> (r+0,k0)/(r+8,k0)/(r+0,k8)/(r+8,k8)
    const uint32_t aLM = sb + SM_A0 +
        (uint32_t)((wm * 64 + (lid & 7) + 8 * ((lid >> 3) & 1)) * ROWB
                   + (lid >> 4) * 16);
    // B x4 (16 n-rows x 16 k): groups -> (n+0,k0)/(n+0,k8)/(n+8,k0)/(n+8,k8)
    const uint32_t bLM = sb + SM_BF0 +
        (uint32_t)((wn * 32 + (lid & 7) + 8 * (lid >> 4)) * ROWB
                   + ((lid >> 3) & 1) * 16);

    // ---- main loop --------------------------------------------------------
    // Invariant at top of iter s: Bf(s&1) holds converted stage s (visible
    // via the trailing barrier), A slot s%4 holds stage s, stages <= s+1
    // have arrived (own-thread groups), stages <= s+2 committed.
#pragma unroll 1
    for (int s = 0; s < NST; s++) {
        // prefetch stage s+3 into A slot (s+3)&3, BI slot (s+3)%3.
        // Prior users (compute(s-1) / convert(s) resp.) retired before the
        // barrier at the end of iter s-1.
        if (s + 3 < NST) {
            const int ps = s + 3;
            const uint32_t ab = sb + SM_A0  + (ps & 3) * A_STAGE_B;
            const uint32_t bb = sb + SM_BI0 + (ps % 3) * BI_STAGE_B;
            const int kb = ps * KC;
#pragma unroll
            for (int i = 0; i < 2; i++) CP_ASYNC16(ab + aSoff[i], aG[i] + kb);
#pragma unroll
            for (int i = 0; i < 4; i++) CP_ASYNC16(bb + bIoff[i], bG[i] + kb);
            CP_COMMIT();
        }
        // ensure stage s+1 arrived (committed: <= s+3; keep last 2 in flight)
        CP_WAIT(2);

        // convert stage s+1 -> Bf parity (s+1)&1 (own chunks only; the
        // same-parity reader compute(s-1) retired before barrier(s-1)).
        if (s + 1 < NST) {
            char* bi = smem + SM_BI0 + ((s + 1) % 3) * BI_STAGE_B;
            char* bf = smem + SM_BF0 + ((s + 1) & 1) * BF_BUF_B;
#pragma unroll
            for (int i = 0; i < 4; i++) {
                int4 v = *reinterpret_cast<const int4*>(bi + bIoff[i]);
                uint2 p;
                p.x = int2_to_h2((uint32_t)v.x, (uint32_t)v.y);
                p.y = int2_to_h2((uint32_t)v.z, (uint32_t)v.w);
                *reinterpret_cast<uint2*>(bf + bFoff[i]) = p;
            }
        }

        // compute stage s: two k16 steps, fragments via ldmatrix.x4
        const uint32_t aS = aLM + (s & 3) * A_STAGE_B;
        const uint32_t bS = bLM + (s & 1) * BF_BUF_B;
#pragma unroll
        for (int kk = 0; kk < 2; kk++) {
            const uint32_t ko = (uint32_t)(kk * 32);
            uint32_t a[4][4], b[4][2];
#pragma unroll
            for (int i = 0; i < 4; i++)
                LDMX4(a[i][0], a[i][1], a[i][2], a[i][3],
                      aS + (uint32_t)(i * 16 * ROWB) + ko);
#pragma unroll
            for (int jp = 0; jp < 2; jp++)
                LDMX4(b[2 * jp][0], b[2 * jp][1], b[2 * jp + 1][0], b[2 * jp + 1][1],
                      bS + (uint32_t)(jp * 16 * ROWB) + ko);
#pragma unroll
            for (int i = 0; i < 4; i++)
#pragma unroll
                for (int j = 0; j < 4; j++)
                    mma_f16(acc[i][j], a[i], b[j]);
        }

        __syncthreads();   // publishes convert(s+1) + guards slot reuse
    }

    // ---- epilogue ---------------------------------------------------------
    const float* s_sc = (const float*)(smem + SM_SCALE);
    const float* s_bi = (const float*)(smem + SM_BIAS);
#pragma unroll
    for (int i = 0; i < 4; i++) {
        const int m = m0 + wm * 64 + i * 16 + g;
#pragma unroll
        for (int j = 0; j < 4; j++) {
            const int nl = wn * 32 + j * 8 + 2 * t;
            const float sc0 = s_sc[nl],     bi0 = s_bi[nl];
            const float sc1 = s_sc[nl + 1], bi1 = s_bi[nl + 1];
            float2 v0 = { acc[i][j][0] * sc0 + bi0, acc[i][j][1] * sc1 + bi1 };
            float2 v1 = { acc[i][j][2] * sc0 + bi0, acc[i][j][3] * sc1 + bi1 };
            *reinterpret_cast<float2*>(out + (size_t)m * OUT_F + n0 + nl) = v0;
            *reinterpret_cast<float2*>(out + (size_t)(m + 8) * OUT_F + n0 + nl) = v1;
        }
    }
}

// ---------------------------------------------------------------------------
extern "C" void kernel_launch(void* const* d_in, const int* in_sizes, int n_in,
                              void* d_out, int out_size) {
    const float* x     = (const float*)d_in[0];
    const int*   W     = (const int*)  d_in[1];
    const float* scale = (const float*)d_in[2];
    const float* bias  = (const float*)d_in[3];
    float*       out   = (float*)d_out;

    (void)in_sizes; (void)n_in; (void)out_size;

    cudaFuncSetAttribute(qlin_gemm_kernel,
                         cudaFuncAttributeMaxDynamicSharedMemorySize, SM_TOTAL);

    prep_x_kernel<<<(TOKENS * IN_F + 255) / 256, 256>>>(x);

    dim3 grid(OUT_F / N_TILE, TOKENS / M_TILE);   // (112, 2) -> 2 CTAs/SM
    qlin_gemm_kernel<<<grid, NTHREADS, SM_TOTAL>>>(W, scale, bias, out);
}